// round 13
// baseline (speedup 1.0000x reference)
#include <cuda_runtime.h>

// MeshfreeKANNet: u[m] = (sum_n phi_win[m,n]*w[n]) / (sum_n phi_win[m,n] + 1e-10)
// Warp per point (4096 warps; occ grid-capped ~43%); ballot-compaction of
// in-radius (~7%) nodes; dense KAN eval.
// R13: fused dual-pair pipeline. The ILP-2 loop (R11) called pair_phi twice,
// re-loading the 32 LDS.128 weight vectors per pair. Now one h-loop loads
// each weight row once and advances TWO independent hv/phi chains.
// Each pair's FMA order is bit-identical to R5/R11 (h asc, s asc); S/Sw
// accumulate A-then-B with predicated zero adds -> bit-exact result.

#define MM      4096
#define NN      1024
#define HIDN    8
#define WARPS   8
#define THREADS 256
#define BLOCKS  (MM / WARPS)

#define R2_F     0.09f
#define INV_R    (1.0f / 0.3f)
#define INV_H    (1.0f / 0.75f)

typedef float4 f4;

__global__ __launch_bounds__(THREADS, 4)
void meshfree_kan_kernel(const float* __restrict__ x,
                         const float* __restrict__ nodes,
                         const float* __restrict__ W1a,
                         const float* __restrict__ W1b,
                         const float* __restrict__ W2,
                         const float* __restrict__ w,
                         float* __restrict__ out)
{
    __shared__ float2 s_nxy[NN];
    __shared__ float  s_w[NN];
    __shared__ f4     s_Wp[HIDN][4];   // {W1a[h][0..4], W1b[h][0..4], W2[h][0..4], 0}
    __shared__ unsigned short s_buf[WARPS][NN];

    const int tid = threadIdx.x;

    for (int i = tid; i < NN; i += THREADS) {
        s_nxy[i] = ((const float2*)nodes)[i];
        s_w[i]   = w[i];
    }
    if (tid < HIDN * 16) {
        const int h = tid >> 4;
        const int e = tid & 15;
        float v = 0.0f;
        if (e < 5)       v = W1a[h * 5 + e];
        else if (e < 10) v = W1b[h * 5 + (e - 5)];
        else if (e < 15) v = W2 [h * 5 + (e - 10)];
        ((float*)s_Wp)[tid] = v;
    }
    __syncthreads();

    const int warp = tid >> 5;
    const int lane = tid & 31;
    const int m = blockIdx.x * WARPS + warp;

    const float px = x[2 * m];
    const float py = x[2 * m + 1];

    const float gridv[5] = {-1.5f, -0.75f, 0.0f, 0.75f, 1.5f};

    // ---- Phase 1: distance filter + warp stream compaction ----
    int cnt = 0;
    const unsigned lmask = (1u << lane) - 1u;
    #pragma unroll 4
    for (int base = 0; base < NN; base += 32) {
        const int n = base + lane;
        const float2 nd = s_nxy[n];
        const float dx = px - nd.x;
        const float dy = py - nd.y;
        const float d2 = fmaf(dx, dx, dy * dy);
        const bool hit = (d2 <= R2_F);
        const unsigned msk = __ballot_sync(0xffffffffu, hit);
        if (hit) s_buf[warp][cnt + __popc(msk & lmask)] = (unsigned short)n;
        cnt += __popc(msk);
    }
    __syncwarp();

    // ---- Phase 2: fused dual-pair pipeline ----
    float S = 0.0f, Sw = 0.0f;
    for (int base = 0; base < cnt; base += 64) {
        const int iA = base + lane;
        const int iB = iA + 32;
        const bool vA = (iA < cnt);
        const bool vB = (iB < cnt);
        // clamped indices keep loads in-bounds; results predicated out below
        const int nA = (int)s_buf[warp][vA ? iA : 0];
        const int nB = (int)s_buf[warp][vB ? iB : 0];

        const float2 ndA = s_nxy[nA];
        const float2 ndB = s_nxy[nB];
        const float dxA = px - ndA.x, dyA = py - ndA.y;
        const float dxB = px - ndB.x, dyB = py - ndB.y;
        const float d2A = fmaf(dxA, dxA, dyA * dyA);
        const float d2B = fmaf(dxB, dxB, dyB * dyB);
        const float kxA = dxA * INV_R, kyA = dyA * INV_R;
        const float kxB = dxB * INV_R, kyB = dyB * INV_R;

        // hat bases for both pairs (reference formulation, bit-exact)
        float baA[5], bbA[5], baB[5], bbB[5];
        #pragma unroll
        for (int s = 0; s < 5; s++) {
            baA[s] = fmaxf(0.0f, 1.0f - fabsf(kxA - gridv[s]) * INV_H);
            bbA[s] = fmaxf(0.0f, 1.0f - fabsf(kyA - gridv[s]) * INV_H);
            baB[s] = fmaxf(0.0f, 1.0f - fabsf(kxB - gridv[s]) * INV_H);
            bbB[s] = fmaxf(0.0f, 1.0f - fabsf(kyB - gridv[s]) * INV_H);
        }

        // single h-loop: weights loaded once, two independent chains
        float phiA = 0.0f, phiB = 0.0f;
        #pragma unroll
        for (int h = 0; h < HIDN; h++) {
            const f4 q0 = s_Wp[h][0];
            const f4 q1 = s_Wp[h][1];
            const f4 q2 = s_Wp[h][2];
            const f4 q3 = s_Wp[h][3];
            const float wa[5]  = {q0.x, q0.y, q0.z, q0.w, q1.x};
            const float wb[5]  = {q1.y, q1.z, q1.w, q2.x, q2.y};
            const float w2r[5] = {q2.z, q2.w, q3.x, q3.y, q3.z};

            float hvA = 0.0f, hvB = 0.0f;
            #pragma unroll
            for (int s = 0; s < 5; s++) {
                hvA = fmaf(baA[s], wa[s], hvA);
                hvA = fmaf(bbA[s], wb[s], hvA);
                hvB = fmaf(baB[s], wa[s], hvB);
                hvB = fmaf(bbB[s], wb[s], hvB);
            }
            #pragma unroll
            for (int s = 0; s < 5; s++) {
                const float bhA = fmaxf(0.0f, 1.0f - fabsf(hvA - gridv[s]) * INV_H);
                const float bhB = fmaxf(0.0f, 1.0f - fabsf(hvB - gridv[s]) * INV_H);
                phiA = fmaf(bhA, w2r[s], phiA);
                phiB = fmaf(bhB, w2r[s], phiB);
            }
        }

        const float qA = sqrtf(d2A) * INV_R;
        const float qB = sqrtf(d2B) * INV_R;
        const float winA = fmaf(qA * qA, fmaf(fmaf(-3.0f, qA, 8.0f), qA, -6.0f), 1.0f);
        const float winB = fmaf(qB * qB, fmaf(fmaf(-3.0f, qB, 8.0f), qB, -6.0f), 1.0f);

        const float pA = vA ? (phiA * winA) : 0.0f;
        const float pB = vB ? (phiB * winB) : 0.0f;
        const float wA = vA ? s_w[nA] : 0.0f;
        const float wB = vB ? s_w[nB] : 0.0f;

        // A then B, matching R11's accumulation order (bit-exact)
        S  += pA;
        Sw  = fmaf(pA, wA, Sw);
        S  += pB;
        Sw  = fmaf(pB, wB, Sw);
    }

    // ---- Warp reduction + normalize ----
    #pragma unroll
    for (int o = 16; o > 0; o >>= 1) {
        S  += __shfl_xor_sync(0xffffffffu, S,  o);
        Sw += __shfl_xor_sync(0xffffffffu, Sw, o);
    }
    if (lane == 0) out[m] = Sw / (S + 1e-10f);
}

extern "C" void kernel_launch(void* const* d_in, const int* in_sizes, int n_in,
                              void* d_out, int out_size)
{
    const float* x     = (const float*)d_in[0];   // [4096, 2]
    const float* nodes = (const float*)d_in[1];   // [1024, 2]
    const float* W1a   = (const float*)d_in[2];   // [8, 5]
    const float* W1b   = (const float*)d_in[3];   // [8, 5]
    const float* W2    = (const float*)d_in[4];   // [1, 40]
    const float* w     = (const float*)d_in[5];   // [1024, 1]
    float* out = (float*)d_out;                   // [4096, 1]

    meshfree_kan_kernel<<<BLOCKS, THREADS>>>(x, nodes, W1a, W1b, W2, w, out);
}